// round 6
// baseline (speedup 1.0000x reference)
#include <cuda_runtime.h>
#include <cuda_bf16.h>

// CGA motor sandwich out = grade1(M * P * ~M)[:, :6], Cl(7,1), B=1024.
// Compile-time tables. 128-thread block handles TWO batch elements:
//   - table LDG.128s loaded once, reused for both batches (2x ILP)
//   - stage 1: one odd-grade bin per thread, both batches
//   - stage 2: 12 tasks (batch,k) over 4 warps; each warp reduces a full
//     127-term dot product (5 shfl levels), lane 0 writes out directly.
//   - signs applied by XOR into the float sign bit (no predicated selects).

#define NM 127

struct Tables {
    int bin[128 * 8];   // a(7b) | p(3b)<<7 | neg<<10
    int s2[6 * 128];    // [k][lane*4+i] = ent for term b=i*32+lane: bin(7b)|neg<<7
};

__host__ __device__ constexpr int popc8(int m) {
    int c = 0;
    for (int i = 0; i < 8; i++) c += (m >> i) & 1;
    return c;
}

__host__ __device__ constexpr int sign_of(int a, int b) {
    int s = 1;
    int aa = a >> 1;
    while (aa) { if (popc8(aa & b) & 1) s = -s; aa >>= 1; }
    if ((a & b) & 0x80) s = -s;   // metric: only basis vector 7 squares to -1
    return s;
}

__host__ __device__ constexpr Tables make_tables() {
    Tables T{};
    int masks[256] = {};
    int t = 0;
    for (int g = 0; g <= 8; ++g)
        for (int m = 0; m < 256; ++m)
            if (popc8(m) == g) masks[t++] = m;

    int mmmask[127] = {};  int mmrank[256] = {};  int nm = 0;
    int oddmask[128] = {}; int binrank[256] = {}; int nodd = 0;
    for (int i = 0; i < 256; ++i) {
        int m = masks[i], g = popc8(m);
        if ((g & 1) == 0 && m != 255) { mmmask[nm] = m; mmrank[m] = nm; ++nm; }
        if (g & 1)                    { oddmask[nodd] = m; binrank[m] = nodd; ++nodd; }
    }

    // stage-1 bins
    for (int bi = 0; bi < 128; ++bi) {
        int rm = oddmask[bi];
        for (int b = 0; b < 8; ++b) {
            int pmask = 1 << b;
            int am = rm ^ pmask;
            int ent = 0;
            if (am == 255) {
                ent = 127;                 // pseudoscalar -> sm[127]==0
            } else {
                int a = mmrank[am];
                int s = sign_of(am, pmask);
                ent = a | (b << 7) | ((s < 0 ? 1 : 0) << 10);
            }
            T.bin[bi * 8 + b] = ent;
        }
    }

    // stage 2, transposed: entry for (k, term b=i*32+lane) at s2[k*128 + lane*4 + i]
    for (int k = 0; k < 6; ++k) {
        for (int b = 0; b < 128; ++b) {
            int ent = 0;
            if (b < NM) {
                int jm = mmmask[b];
                int im = (1 << k) ^ jm;
                int bi = binrank[im];
                int g  = popc8(jm);
                int rs = ((g * (g - 1) / 2) & 1) ? -1 : 1;   // reverse sign
                int s  = sign_of(im, jm) * rs;
                ent = bi | ((s < 0 ? 1 : 0) << 7);
            }                               // b==127 pad: smx[0]*sm[127]==0
            int lane = b & 31, i = b >> 5;
            T.s2[k * 128 + lane * 4 + i] = ent;
        }
    }
    return T;
}

__device__ const Tables g_T = make_tables();

__global__ __launch_bounds__(128)
void cga_sandwich_kernel(const float* __restrict__ motor,
                         const float* __restrict__ x,
                         float* __restrict__ out,
                         int Bn)
{
    __shared__ float sm[2][128];
    __shared__ float sp[2][8];
    __shared__ float smx[2][128];

    const int t = threadIdx.x;
    const int b0 = blockIdx.x * 2;
    const int b1 = (b0 + 1 < Bn) ? b0 + 1 : b0;

    // coalesced motor loads (2 independent LDGs), pad slot 127 = 0
    sm[0][t] = (t < NM) ? motor[(size_t)b0 * NM + t] : 0.0f;
    sm[1][t] = (t < NM) ? motor[(size_t)b1 * NM + t] : 0.0f;

    // points: threads 0..7 -> batch0, 8..15 -> batch1
    if (t < 16) {
        const int g = t >> 3, j = t & 7;
        const float* xr = x + (size_t)(g ? b1 : b0) * 6;
        float h = 0.0f;
        #pragma unroll
        for (int i = 0; i < 6; i++) { float v = xr[i]; h += v * v; }
        h *= 0.5f;
        sp[g][j] = (j < 6) ? xr[j] : (j == 6 ? h - 0.5f : h + 0.5f);
    }
    __syncthreads();

    // ---- stage 1: bin t for both batches; table loaded once ----
    {
        const int4* bt = (const int4*)(g_T.bin + t * 8);
        int4 e0 = __ldg(bt);
        int4 e1 = __ldg(bt + 1);
        float a0 = 0.f, a1 = 0.f;
        #define S1T(ent) { \
            int _a = (ent) & 127; \
            int _p = ((ent) >> 7) & 7; \
            unsigned _s = ((unsigned)((ent) & 1024)) << 21; \
            a0 = fmaf(__int_as_float(__float_as_int(sm[0][_a]) ^ _s), sp[0][_p], a0); \
            a1 = fmaf(__int_as_float(__float_as_int(sm[1][_a]) ^ _s), sp[1][_p], a1); }
        S1T(e0.x) S1T(e0.y) S1T(e0.z) S1T(e0.w)
        S1T(e1.x) S1T(e1.y) S1T(e1.z) S1T(e1.w)
        #undef S1T
        smx[0][t] = a0;
        smx[1][t] = a1;
    }
    __syncthreads();

    // ---- stage 2: 12 tasks (batch,k) over 4 warps, 3 each ----
    const int w = t >> 5, lane = t & 31;
    #pragma unroll
    for (int task = w; task < 12; task += 4) {
        const int bat = (task >= 6) ? 1 : 0;
        const int k   = task - bat * 6;
        const int4 f = __ldg((const int4*)(g_T.s2 + k * 128 + lane * 4));
        const float* smb  = sm[bat];
        const float* smxb = smx[bat];
        float acc;
        {
            float v = __int_as_float(__float_as_int(smxb[f.x & 127]) ^ (((unsigned)(f.x & 128)) << 24));
            acc = v * smb[lane];
        }
        {
            float v = __int_as_float(__float_as_int(smxb[f.y & 127]) ^ (((unsigned)(f.y & 128)) << 24));
            acc = fmaf(v, smb[32 + lane], acc);
        }
        {
            float v = __int_as_float(__float_as_int(smxb[f.z & 127]) ^ (((unsigned)(f.z & 128)) << 24));
            acc = fmaf(v, smb[64 + lane], acc);
        }
        {
            float v = __int_as_float(__float_as_int(smxb[f.w & 127]) ^ (((unsigned)(f.w & 128)) << 24));
            acc = fmaf(v, smb[96 + lane], acc);
        }
        #pragma unroll
        for (int off = 16; off; off >>= 1)
            acc += __shfl_xor_sync(0xffffffffu, acc, off);
        if (lane == 0)
            out[(size_t)(bat ? b1 : b0) * 6 + k] = acc;
    }
}

extern "C" void kernel_launch(void* const* d_in, const int* in_sizes, int n_in,
                              void* d_out, int out_size)
{
    const float* motor = (const float*)d_in[0];   // [B, 127]
    const float* x     = (const float*)d_in[1];   // [B, 6]
    float* out = (float*)d_out;

    int Bn = in_sizes[0] / NM;                    // 1024
    int grid = (Bn + 1) / 2;                      // 2 batches per 128-thread block
    cga_sandwich_kernel<<<grid, 128>>>(motor, x, out, Bn);
}